// round 15
// baseline (speedup 1.0000x reference)
#include <cuda_runtime.h>
#include <math.h>

#define PI_F 3.14159265358979323846f

static const int B = 32, C = 4, H = 512, W = 512;

__device__ __forceinline__ float clampf_(float v, float lo, float hi) {
    return fminf(fmaxf(v, lo), hi);
}

// ---------------------------------------------------------------------------
// Final kernel — measured local optimum across ten controlled variants:
//  - per-thread recompute of fwd/inv affine matrices from fc2 (fp32)
//  - writes grid + inv_grid (float2); mat/inv_mat from one block
//  - bilinear-samples 4 channels with zero padding folded into tap weights
//    (16 scalar LDG.32 gathers: minimal L1 wavefronts for scattered access)
// Warp tile: 8 wide x 4 tall (compact rotated source footprint). Block 32x8.
// ---------------------------------------------------------------------------
__global__ __launch_bounds__(256)
void fused_affine_kernel(const float* __restrict__ src,
                         const float* __restrict__ fc2,
                         float* __restrict__ out_trans,
                         float* __restrict__ out_mat,
                         float* __restrict__ out_inv,
                         float* __restrict__ out_grid,
                         float* __restrict__ out_invgrid) {
    const int b = blockIdx.z;

    // --- rebuild matrices in registers (uniform across block; L1-broadcast) ---
    const float* __restrict__ f = fc2 + b * 7;
    float f0 = __ldg(&f[0]), f1 = __ldg(&f[1]), f2 = __ldg(&f[2]);
    float f3 = __ldg(&f[3]), f4 = __ldg(&f[4]), f5 = __ldg(&f[5]);
    float f6 = __ldg(&f[6]);

    const float theta = clampf_(f0 * 0.3f, -1.f, 1.f) * PI_F;
    const float sx = clampf_(f1 * 0.3f + 1.0f, 0.f, 5.f);
    const float sy = clampf_(f2 * 0.3f + 1.0f, 0.f, 5.f);
    const float tx = f3 * 0.3f;
    const float ty = f4 * 0.3f;
    const float shxy = clampf_(f5 * 0.3f, -1.f, 1.f) * PI_F;
    const float shyx = clampf_(f6 * 0.3f, -1.f, 1.f) * PI_F;

    const float c = cosf(theta), s = sinf(theta);
    // mat = trn @ shr @ scl @ rot = [[a,bb,tx],[d,e,ty],[0,0,1]]
    const float a  = fmaf(shxy * sy, s, sx * c);
    const float bb = fmaf(shxy * sy, c, -sx * s);
    const float d  = fmaf(shyx * sx, c, sy * s);
    const float e  = fmaf(-shyx * sx, s, sy * c);

    const float det = fmaf(a, e, -bb * d);
    const float rdet = 1.0f / det;
    const float ia  = e * rdet;
    const float ib  = -bb * rdet;
    const float itx = fmaf(bb, ty, -e * tx) * rdet;
    const float id  = -d * rdet;
    const float ie  = a * rdet;
    const float ity = fmaf(d, tx, -a * ty) * rdet;

    if (blockIdx.x == 0 && blockIdx.y == 0 && threadIdx.x == 0) {
        float* om = out_mat + b * 9;
        om[0] = a;  om[1] = bb; om[2] = tx;
        om[3] = d;  om[4] = e;  om[5] = ty;
        om[6] = 0.f; om[7] = 0.f; om[8] = 1.f;
        float* oi = out_inv + b * 9;
        oi[0] = ia; oi[1] = ib; oi[2] = itx;
        oi[3] = id; oi[4] = ie; oi[5] = ity;
        oi[6] = 0.f; oi[7] = 0.f; oi[8] = 1.f;
    }

    // --- pixel coordinates: 8x4 warp tile, 32x8 block tile ---
    const int tid = threadIdx.x;
    const int lane = tid & 31;
    const int warp = tid >> 5;
    const int lx = lane & 7;
    const int ly = lane >> 3;
    const int wx = warp & 3;
    const int wy = warp >> 2;

    const int w = blockIdx.x * 32 + wx * 8 + lx;
    const int h = blockIdx.y * 8 + wy * 4 + ly;
    const int pix = h * W + w;

    const float x = (2.0f * (float)w + 1.0f) * (1.0f / (float)W) - 1.0f;
    const float y = (2.0f * (float)h + 1.0f) * (1.0f / (float)H) - 1.0f;

    const float gx = fmaf(a, x, fmaf(bb, y, tx));
    const float gy = fmaf(d, x, fmaf(e, y, ty));
    const float igx = fmaf(ia, x, fmaf(ib, y, itx));
    const float igy = fmaf(id, x, fmaf(ie, y, ity));

    const size_t gidx = (size_t)b * (H * W) + (size_t)pix;
    reinterpret_cast<float2*>(out_grid)[gidx]    = make_float2(gx, gy);
    reinterpret_cast<float2*>(out_invgrid)[gidx] = make_float2(igx, igy);

    // --- bilinear sample with zero padding ---
    const float ixf = ((gx + 1.0f) * (float)W - 1.0f) * 0.5f;
    const float iyf = ((gy + 1.0f) * (float)H - 1.0f) * 0.5f;
    const float x0f = floorf(ixf);
    const float y0f = floorf(iyf);
    const float wxf = ixf - x0f;
    const float wyf = iyf - y0f;
    const int x0 = (int)x0f;
    const int y0 = (int)y0f;
    const int x1 = x0 + 1;
    const int y1 = y0 + 1;

    const float vx0 = (x0 >= 0 && x0 < W) ? 1.0f : 0.0f;
    const float vx1 = (x1 >= 0 && x1 < W) ? 1.0f : 0.0f;
    const float vy0 = (y0 >= 0 && y0 < H) ? 1.0f : 0.0f;
    const float vy1 = (y1 >= 0 && y1 < H) ? 1.0f : 0.0f;

    const int cx0 = min(max(x0, 0), W - 1);
    const int cx1 = min(max(x1, 0), W - 1);
    const int cy0 = min(max(y0, 0), H - 1);
    const int cy1 = min(max(y1, 0), H - 1);

    const float w00 = (1.0f - wxf) * (1.0f - wyf) * vx0 * vy0;
    const float w01 = wxf * (1.0f - wyf) * vx1 * vy0;
    const float w10 = (1.0f - wxf) * wyf * vx0 * vy1;
    const float w11 = wxf * wyf * vx1 * vy1;

    const int off00 = cy0 * W + cx0;
    const int off01 = cy0 * W + cx1;
    const int off10 = cy1 * W + cx0;
    const int off11 = cy1 * W + cx1;

    const float* __restrict__ sb = src + (size_t)b * C * H * W;
    float* __restrict__ ob = out_trans + (size_t)b * C * H * W;

#pragma unroll
    for (int ch = 0; ch < C; ch++) {
        const float* __restrict__ img = sb + (size_t)ch * (H * W);
        float v00 = __ldg(&img[off00]);
        float v01 = __ldg(&img[off01]);
        float v10 = __ldg(&img[off10]);
        float v11 = __ldg(&img[off11]);
        float r = fmaf(v00, w00, fmaf(v01, w01, fmaf(v10, w10, v11 * w11)));
        ob[(size_t)ch * (H * W) + pix] = r;
    }
}

extern "C" void kernel_launch(void* const* d_in, const int* in_sizes, int n_in,
                              void* d_out, int out_size) {
    const float* src = (const float*)d_in[0];
    const float* fc2 = (const float*)d_in[1];
    float* out = (float*)d_out;

    // output layout: transformed | mat | inv_mat | grid | inv_grid
    const size_t n_trans = (size_t)B * C * H * W;          // 33,554,432
    const size_t n_mat = (size_t)B * 9;                    // 288
    const size_t n_grid = (size_t)B * H * W * 2;           // 16,777,216

    float* out_trans = out;
    float* out_mat   = out + n_trans;
    float* out_inv   = out_mat + n_mat;
    float* out_grid  = out_inv + n_mat;
    float* out_igrid = out_grid + n_grid;

    dim3 grid(W / 32, H / 8, B);
    fused_affine_kernel<<<grid, 256>>>(src, fc2, out_trans, out_mat, out_inv,
                                       out_grid, out_igrid);
}

// round 16
// speedup vs baseline: 1.5897x; 1.5897x over previous
#include <cuda_runtime.h>
#include <math.h>

#define PI_F 3.14159265358979323846f

static const int B = 32, C = 4, H = 512, W = 512;

__device__ __forceinline__ float clampf_(float v, float lo, float hi) {
    return fminf(fmaxf(v, lo), hi);
}

// ---------------------------------------------------------------------------
// Final kernel — measured local optimum across ten controlled variants:
//  - per-thread recompute of fwd/inv affine matrices from fc2 (fp32)
//  - writes grid + inv_grid (float2); mat/inv_mat from one block
//  - bilinear-samples 4 channels with zero padding folded into tap weights
//    (16 scalar LDG.32 gathers: minimal L1 wavefronts for scattered access)
// Warp tile: 8 wide x 4 tall (compact rotated source footprint). Block 32x8.
// ---------------------------------------------------------------------------
__global__ __launch_bounds__(256)
void fused_affine_kernel(const float* __restrict__ src,
                         const float* __restrict__ fc2,
                         float* __restrict__ out_trans,
                         float* __restrict__ out_mat,
                         float* __restrict__ out_inv,
                         float* __restrict__ out_grid,
                         float* __restrict__ out_invgrid) {
    const int b = blockIdx.z;

    // --- rebuild matrices in registers (uniform across block; L1-broadcast) ---
    const float* __restrict__ f = fc2 + b * 7;
    float f0 = __ldg(&f[0]), f1 = __ldg(&f[1]), f2 = __ldg(&f[2]);
    float f3 = __ldg(&f[3]), f4 = __ldg(&f[4]), f5 = __ldg(&f[5]);
    float f6 = __ldg(&f[6]);

    const float theta = clampf_(f0 * 0.3f, -1.f, 1.f) * PI_F;
    const float sx = clampf_(f1 * 0.3f + 1.0f, 0.f, 5.f);
    const float sy = clampf_(f2 * 0.3f + 1.0f, 0.f, 5.f);
    const float tx = f3 * 0.3f;
    const float ty = f4 * 0.3f;
    const float shxy = clampf_(f5 * 0.3f, -1.f, 1.f) * PI_F;
    const float shyx = clampf_(f6 * 0.3f, -1.f, 1.f) * PI_F;

    const float c = cosf(theta), s = sinf(theta);
    // mat = trn @ shr @ scl @ rot = [[a,bb,tx],[d,e,ty],[0,0,1]]
    const float a  = fmaf(shxy * sy, s, sx * c);
    const float bb = fmaf(shxy * sy, c, -sx * s);
    const float d  = fmaf(shyx * sx, c, sy * s);
    const float e  = fmaf(-shyx * sx, s, sy * c);

    const float det = fmaf(a, e, -bb * d);
    const float rdet = 1.0f / det;
    const float ia  = e * rdet;
    const float ib  = -bb * rdet;
    const float itx = fmaf(bb, ty, -e * tx) * rdet;
    const float id  = -d * rdet;
    const float ie  = a * rdet;
    const float ity = fmaf(d, tx, -a * ty) * rdet;

    if (blockIdx.x == 0 && blockIdx.y == 0 && threadIdx.x == 0) {
        float* om = out_mat + b * 9;
        om[0] = a;  om[1] = bb; om[2] = tx;
        om[3] = d;  om[4] = e;  om[5] = ty;
        om[6] = 0.f; om[7] = 0.f; om[8] = 1.f;
        float* oi = out_inv + b * 9;
        oi[0] = ia; oi[1] = ib; oi[2] = itx;
        oi[3] = id; oi[4] = ie; oi[5] = ity;
        oi[6] = 0.f; oi[7] = 0.f; oi[8] = 1.f;
    }

    // --- pixel coordinates: 8x4 warp tile, 32x8 block tile ---
    const int tid = threadIdx.x;
    const int lane = tid & 31;
    const int warp = tid >> 5;
    const int lx = lane & 7;
    const int ly = lane >> 3;
    const int wx = warp & 3;
    const int wy = warp >> 2;

    const int w = blockIdx.x * 32 + wx * 8 + lx;
    const int h = blockIdx.y * 8 + wy * 4 + ly;
    const int pix = h * W + w;

    const float x = (2.0f * (float)w + 1.0f) * (1.0f / (float)W) - 1.0f;
    const float y = (2.0f * (float)h + 1.0f) * (1.0f / (float)H) - 1.0f;

    const float gx = fmaf(a, x, fmaf(bb, y, tx));
    const float gy = fmaf(d, x, fmaf(e, y, ty));
    const float igx = fmaf(ia, x, fmaf(ib, y, itx));
    const float igy = fmaf(id, x, fmaf(ie, y, ity));

    const size_t gidx = (size_t)b * (H * W) + (size_t)pix;
    reinterpret_cast<float2*>(out_grid)[gidx]    = make_float2(gx, gy);
    reinterpret_cast<float2*>(out_invgrid)[gidx] = make_float2(igx, igy);

    // --- bilinear sample with zero padding ---
    const float ixf = ((gx + 1.0f) * (float)W - 1.0f) * 0.5f;
    const float iyf = ((gy + 1.0f) * (float)H - 1.0f) * 0.5f;
    const float x0f = floorf(ixf);
    const float y0f = floorf(iyf);
    const float wxf = ixf - x0f;
    const float wyf = iyf - y0f;
    const int x0 = (int)x0f;
    const int y0 = (int)y0f;
    const int x1 = x0 + 1;
    const int y1 = y0 + 1;

    const float vx0 = (x0 >= 0 && x0 < W) ? 1.0f : 0.0f;
    const float vx1 = (x1 >= 0 && x1 < W) ? 1.0f : 0.0f;
    const float vy0 = (y0 >= 0 && y0 < H) ? 1.0f : 0.0f;
    const float vy1 = (y1 >= 0 && y1 < H) ? 1.0f : 0.0f;

    const int cx0 = min(max(x0, 0), W - 1);
    const int cx1 = min(max(x1, 0), W - 1);
    const int cy0 = min(max(y0, 0), H - 1);
    const int cy1 = min(max(y1, 0), H - 1);

    const float w00 = (1.0f - wxf) * (1.0f - wyf) * vx0 * vy0;
    const float w01 = wxf * (1.0f - wyf) * vx1 * vy0;
    const float w10 = (1.0f - wxf) * wyf * vx0 * vy1;
    const float w11 = wxf * wyf * vx1 * vy1;

    const int off00 = cy0 * W + cx0;
    const int off01 = cy0 * W + cx1;
    const int off10 = cy1 * W + cx0;
    const int off11 = cy1 * W + cx1;

    const float* __restrict__ sb = src + (size_t)b * C * H * W;
    float* __restrict__ ob = out_trans + (size_t)b * C * H * W;

#pragma unroll
    for (int ch = 0; ch < C; ch++) {
        const float* __restrict__ img = sb + (size_t)ch * (H * W);
        float v00 = __ldg(&img[off00]);
        float v01 = __ldg(&img[off01]);
        float v10 = __ldg(&img[off10]);
        float v11 = __ldg(&img[off11]);
        float r = fmaf(v00, w00, fmaf(v01, w01, fmaf(v10, w10, v11 * w11)));
        ob[(size_t)ch * (H * W) + pix] = r;
    }
}

extern "C" void kernel_launch(void* const* d_in, const int* in_sizes, int n_in,
                              void* d_out, int out_size) {
    const float* src = (const float*)d_in[0];
    const float* fc2 = (const float*)d_in[1];
    float* out = (float*)d_out;

    // output layout: transformed | mat | inv_mat | grid | inv_grid
    const size_t n_trans = (size_t)B * C * H * W;          // 33,554,432
    const size_t n_mat = (size_t)B * 9;                    // 288
    const size_t n_grid = (size_t)B * H * W * 2;           // 16,777,216

    float* out_trans = out;
    float* out_mat   = out + n_trans;
    float* out_inv   = out_mat + n_mat;
    float* out_grid  = out_inv + n_mat;
    float* out_igrid = out_grid + n_grid;

    dim3 grid(W / 32, H / 8, B);
    fused_affine_kernel<<<grid, 256>>>(src, fc2, out_trans, out_mat, out_inv,
                                       out_grid, out_igrid);
}